// round 1
// baseline (speedup 1.0000x reference)
#include <cuda_runtime.h>
#include <math.h>
#include <stdint.h>

// Problem constants (fixed by the dataset)
#define NN 20000
#define EE 320000
#define EL (EE + NN)      // edges + self loops
#define DIN 128
#define DHID 128
#define DOUT 64
#define HEADS 8
#define GG 64

// ---------------- scratch (no allocations allowed) ----------------
__device__ float g_tmp[NN * DHID];          // pre-aggregation features
__device__ float g_h0[NN * DHID];           // gcn0 output
__device__ float g_h1[NN * DHID];           // gcn1 output
__device__ float g_deg[NN];                 // in-degree (no self loops)
__device__ float g_dinv[NN];                // rsqrt(deg+1)
__device__ float g_gath[NN * HEADS * DOUT]; // h1 @ gat_w   [N,512]
__device__ float g_als[NN * HEADS];
__device__ float g_ald[NN * HEADS];
__device__ float g_logits[EL * HEADS];      // logits, then exp(logit-m)
__device__ float g_m[NN * HEADS];
__device__ float g_denom[NN * HEADS];
__device__ float g_gatout[NN * DOUT];
__device__ float g_agg[NN * DHID];          // sage1 mean-agg
__device__ float g_s1[NN * DOUT];
__device__ float g_agg2[NN * DOUT];
__device__ float g_s2[NN * DOUT];
__device__ float g_emb[NN * DOUT];
__device__ float g_cnt[GG];

// ---------------- GEMM: C[N,K] = A[N,M] @ W[M,K] (+b) (+=) (relu) ----------------
// blockDim.x = K (64/128/512), 8 rows per block, A rows staged in smem (broadcast reads)
__global__ void gemm_kernel(const float* __restrict__ A, const float* __restrict__ W,
                            const float* __restrict__ b, float* __restrict__ C,
                            int N, int M, int K, int accum, int relu) {
    __shared__ float As[8 * 128];
    int row0 = blockIdx.x * 8;
    int col  = threadIdx.x;
    for (int i = threadIdx.x; i < 8 * M; i += blockDim.x) {
        int r = i / M, m = i - r * M;
        As[i] = (row0 + r < N) ? A[(size_t)(row0 + r) * M + m] : 0.f;
    }
    __syncthreads();
    float acc[8];
#pragma unroll
    for (int r = 0; r < 8; r++) acc[r] = 0.f;
    for (int m = 0; m < M; m++) {
        float w = W[(size_t)m * K + col];
#pragma unroll
        for (int r = 0; r < 8; r++) acc[r] += As[r * M + m] * w;
    }
    float bias = b ? b[col] : 0.f;
#pragma unroll
    for (int r = 0; r < 8; r++) {
        int row = row0 + r;
        if (row >= N) continue;
        float v = acc[r] + bias;
        if (accum) v += C[(size_t)row * K + col];
        if (relu) v = fmaxf(v, 0.f);
        C[(size_t)row * K + col] = v;
    }
}

// ---------------- degree / norm ----------------
__global__ void deg_kernel(const int* __restrict__ ei, float* __restrict__ deg, int E) {
    int i = blockIdx.x * blockDim.x + threadIdx.x;
    if (i < E) atomicAdd(&deg[ei[E + i]], 1.f);
}
__global__ void dinv_kernel(const float* __restrict__ deg, float* __restrict__ dinv, int N) {
    int i = blockIdx.x * blockDim.x + threadIdx.x;
    if (i < N) dinv[i] = rsqrtf(deg[i] + 1.f);
}

// ---------------- GCN scatter: out[dst] += tmp[src]*dinv[src]*dinv[dst] (128 ch) ----------------
__global__ void gcn_scatter(const float* __restrict__ tmp, const int* __restrict__ ei,
                            const float* __restrict__ dinv, float* __restrict__ out, int E) {
    int e = blockIdx.x * (blockDim.x >> 5) + (threadIdx.x >> 5);
    if (e >= E) return;
    int lane = threadIdx.x & 31;
    int s = ei[e], d = ei[E + e];
    float nrm = dinv[s] * dinv[d];
    float4 v = ((const float4*)(tmp + (size_t)s * 128))[lane];
    float* o = out + (size_t)d * 128 + lane * 4;
    atomicAdd(o + 0, v.x * nrm);
    atomicAdd(o + 1, v.y * nrm);
    atomicAdd(o + 2, v.z * nrm);
    atomicAdd(o + 3, v.w * nrm);
}
// epilogue: h = relu(agg + tmp*dinv^2 + b)
__global__ void gcn_epilogue(float* __restrict__ h, const float* __restrict__ tmp,
                             const float* __restrict__ dinv, const float* __restrict__ b, int N) {
    int i = blockIdx.x * blockDim.x + threadIdx.x;
    if (i >= N * 128) return;
    int n = i >> 7, c = i & 127;
    float dv = dinv[n];
    float v = h[i] + tmp[i] * dv * dv + b[c];
    h[i] = fmaxf(v, 0.f);
}

// ---------------- GAT ----------------
__global__ void gat_al_kernel(const float* __restrict__ gath, const float* __restrict__ asrc,
                              const float* __restrict__ adst, float* __restrict__ als,
                              float* __restrict__ ald, int N) {
    int i = blockIdx.x * blockDim.x + threadIdx.x;
    if (i >= N * HEADS) return;
    int n = i >> 3, h = i & 7;
    const float4* hp = (const float4*)(gath + (size_t)n * 512 + h * 64);
    const float4* sp = (const float4*)(asrc + h * 64);
    const float4* dp = (const float4*)(adst + h * 64);
    float a = 0.f, b = 0.f;
#pragma unroll
    for (int k = 0; k < 16; k++) {
        float4 hv = hp[k], sv = sp[k], dv = dp[k];
        a += hv.x * sv.x + hv.y * sv.y + hv.z * sv.z + hv.w * sv.w;
        b += hv.x * dv.x + hv.y * dv.y + hv.z * dv.z + hv.w * dv.w;
    }
    als[i] = a;
    ald[i] = b;
}

__device__ __forceinline__ void atomicMaxFloat(float* addr, float val) {
    if (val >= 0.f) atomicMax((int*)addr, __float_as_int(val));
    else            atomicMin((unsigned int*)addr, __float_as_uint(val));
}

__global__ void gat_passA(const int* __restrict__ ei, const float* __restrict__ als,
                          const float* __restrict__ ald, float* __restrict__ logits,
                          float* __restrict__ m, int E) {
    int i = blockIdx.x * blockDim.x + threadIdx.x;
    if (i >= EL * HEADS) return;
    int e = i >> 3, h = i & 7;
    int s, d;
    if (e < E) { s = ei[e]; d = ei[E + e]; } else { s = d = e - E; }
    float l = als[s * 8 + h] + ald[d * 8 + h];
    l = (l > 0.f) ? l : 0.2f * l;
    logits[i] = l;
    atomicMaxFloat(&m[d * 8 + h], l);
}
__global__ void gat_passB(const int* __restrict__ ei, float* __restrict__ logits,
                          const float* __restrict__ m, float* __restrict__ denom, int E) {
    int i = blockIdx.x * blockDim.x + threadIdx.x;
    if (i >= EL * HEADS) return;
    int e = i >> 3, h = i & 7;
    int d = (e < E) ? ei[E + e] : (e - E);
    float ev = __expf(logits[i] - m[d * 8 + h]);
    logits[i] = ev;                       // reuse buffer: now holds exp values
    atomicAdd(&denom[d * 8 + h], ev);
}
// pass C: out[dst,c] += (1/8) * sum_h alpha_h * gath[src, h*64+c]
__global__ void gat_passC(const int* __restrict__ ei, const float* __restrict__ ev,
                          const float* __restrict__ denom, const float* __restrict__ gath,
                          float* __restrict__ out, int E) {
    __shared__ float alpha[4][8];
    int e = blockIdx.x * 4 + threadIdx.y;
    int s = 0, d = 0;
    if (e < EL) {
        if (e < E) { s = ei[e]; d = ei[E + e]; } else { s = d = e - E; }
        if (threadIdx.x < 8) {
            int h = threadIdx.x;
            alpha[threadIdx.y][h] = ev[(size_t)e * 8 + h] / denom[d * 8 + h];
        }
    }
    __syncthreads();
    if (e >= EL) return;
    int c = threadIdx.x;
    const float* hr = gath + (size_t)s * 512;
    float acc = 0.f;
#pragma unroll
    for (int h = 0; h < 8; h++) acc += alpha[threadIdx.y][h] * hr[h * 64 + c];
    atomicAdd(&out[(size_t)d * 64 + c], acc * 0.125f);
}

// ---------------- SAGE scatter (plain sum over real edges) ----------------
__global__ void sage_scatter(const float* __restrict__ x, const int* __restrict__ ei,
                             float* __restrict__ out, int E, int C) {
    int e = blockIdx.x * (blockDim.x >> 5) + (threadIdx.x >> 5);
    if (e >= E) return;
    int lane = threadIdx.x & 31;
    if (lane * 4 >= C) return;
    int s = ei[e], d = ei[E + e];
    float4 v = ((const float4*)(x + (size_t)s * C))[lane];
    float* o = out + (size_t)d * C + lane * 4;
    atomicAdd(o + 0, v.x);
    atomicAdd(o + 1, v.y);
    atomicAdd(o + 2, v.z);
    atomicAdd(o + 3, v.w);
}
__global__ void scale_rows(float* __restrict__ x, const float* __restrict__ deg, int N, int C) {
    int i = blockIdx.x * blockDim.x + threadIdx.x;
    if (i >= N * C) return;
    int n = i / C;
    x[i] *= 1.f / fmaxf(deg[n], 1.f);
}

// ---------------- fills ----------------
__global__ void fill_val(float* p, int n, float v) {
    int i = blockIdx.x * blockDim.x + threadIdx.x;
    if (i < n) p[i] = v;
}
__global__ void fill_bias_rows(float* p, const float* __restrict__ b, int N, int C) {
    int i = blockIdx.x * blockDim.x + threadIdx.x;
    if (i < N * C) p[i] = b[i % C];
}

// ---------------- pooling ----------------
__global__ void pool_sum(const float* __restrict__ emb, const int* __restrict__ batch,
                         float* __restrict__ out, float* __restrict__ cnt, int N) {
    int i = blockIdx.x * blockDim.x + threadIdx.x;
    if (i >= N * 64) return;
    int n = i >> 6, c = i & 63;
    atomicAdd(&out[batch[n] * 64 + c], emb[i]);
    if (c == 0) atomicAdd(&cnt[batch[n]], 1.f);
}
__global__ void pool_div(float* __restrict__ out, const float* __restrict__ cnt, int G) {
    int i = blockIdx.x * blockDim.x + threadIdx.x;
    if (i >= G * 64) return;
    out[i] /= fmaxf(cnt[i >> 6], 1.f);
}

// ---------------- launch ----------------
static void launch_gemm(const float* A, const float* W, const float* b, float* C,
                        int N, int M, int K, int accum, int relu) {
    int grid = (N + 7) / 8;
    gemm_kernel<<<grid, K>>>(A, W, b, C, N, M, K, accum, relu);
}

extern "C" void kernel_launch(void* const* d_in, const int* in_sizes, int n_in,
                              void* d_out, int out_size) {
    const float* x       = (const float*)d_in[0];
    const int*   ei      = (const int*)d_in[1];
    const int*   batch   = (const int*)d_in[2];
    const float* gcn_w0  = (const float*)d_in[3];
    const float* gcn_b0  = (const float*)d_in[4];
    const float* gcn_w1  = (const float*)d_in[5];
    const float* gcn_b1  = (const float*)d_in[6];
    const float* gat_w   = (const float*)d_in[7];
    const float* att_src = (const float*)d_in[8];
    const float* att_dst = (const float*)d_in[9];
    const float* gat_b   = (const float*)d_in[10];
    const float* s1wl    = (const float*)d_in[11];
    const float* s1wr    = (const float*)d_in[12];
    const float* s1b     = (const float*)d_in[13];
    const float* s2wl    = (const float*)d_in[14];
    const float* s2wr    = (const float*)d_in[15];
    const float* s2b     = (const float*)d_in[16];
    const float* projw   = (const float*)d_in[17];
    const float* projb   = (const float*)d_in[18];

    const int N = in_sizes[0] / DIN;
    const int E = in_sizes[1] / 2;
    const int G = out_size / DOUT;
    float* out = (float*)d_out;

    float *tmp, *h0, *h1, *deg, *dinv, *gath, *als, *ald, *logits, *m, *denom,
          *gatout, *agg, *s1, *agg2, *s2, *emb, *cnt;
    cudaGetSymbolAddress((void**)&tmp, g_tmp);
    cudaGetSymbolAddress((void**)&h0, g_h0);
    cudaGetSymbolAddress((void**)&h1, g_h1);
    cudaGetSymbolAddress((void**)&deg, g_deg);
    cudaGetSymbolAddress((void**)&dinv, g_dinv);
    cudaGetSymbolAddress((void**)&gath, g_gath);
    cudaGetSymbolAddress((void**)&als, g_als);
    cudaGetSymbolAddress((void**)&ald, g_ald);
    cudaGetSymbolAddress((void**)&logits, g_logits);
    cudaGetSymbolAddress((void**)&m, g_m);
    cudaGetSymbolAddress((void**)&denom, g_denom);
    cudaGetSymbolAddress((void**)&gatout, g_gatout);
    cudaGetSymbolAddress((void**)&agg, g_agg);
    cudaGetSymbolAddress((void**)&s1, g_s1);
    cudaGetSymbolAddress((void**)&agg2, g_agg2);
    cudaGetSymbolAddress((void**)&s2, g_s2);
    cudaGetSymbolAddress((void**)&emb, g_emb);
    cudaGetSymbolAddress((void**)&cnt, g_cnt);

    const int T = 256;
    int elEdgeBlocks = (E + 7) / 8;  // 8 warps/block, warp per edge

    // degrees + normalization (shared by GCN and SAGE)
    cudaMemsetAsync(deg, 0, N * sizeof(float));
    deg_kernel<<<(E + T - 1) / T, T>>>(ei, deg, E);
    dinv_kernel<<<(N + T - 1) / T, T>>>(deg, dinv, N);

    // ---- GCN layer 0 ----
    launch_gemm(x, gcn_w0, nullptr, tmp, N, DIN, DHID, 0, 0);
    cudaMemsetAsync(h0, 0, (size_t)N * DHID * sizeof(float));
    gcn_scatter<<<elEdgeBlocks, T>>>(tmp, ei, dinv, h0, E);
    gcn_epilogue<<<(N * DHID + T - 1) / T, T>>>(h0, tmp, dinv, gcn_b0, N);

    // ---- GCN layer 1 ----
    launch_gemm(h0, gcn_w1, nullptr, tmp, N, DHID, DHID, 0, 0);
    cudaMemsetAsync(h1, 0, (size_t)N * DHID * sizeof(float));
    gcn_scatter<<<elEdgeBlocks, T>>>(tmp, ei, dinv, h1, E);
    gcn_epilogue<<<(N * DHID + T - 1) / T, T>>>(h1, tmp, dinv, gcn_b1, N);

    // ---- GAT ----
    launch_gemm(h1, gat_w, nullptr, gath, N, DHID, HEADS * DOUT, 0, 0);
    gat_al_kernel<<<(N * HEADS + T - 1) / T, T>>>(gath, att_src, att_dst, als, ald, N);
    fill_val<<<(N * HEADS + T - 1) / T, T>>>(m, N * HEADS, -INFINITY);
    cudaMemsetAsync(denom, 0, N * HEADS * sizeof(float));
    int elItems = (E + N) * HEADS;
    gat_passA<<<(elItems + T - 1) / T, T>>>(ei, als, ald, logits, m, E);
    gat_passB<<<(elItems + T - 1) / T, T>>>(ei, logits, m, denom, E);
    fill_bias_rows<<<(N * DOUT + T - 1) / T, T>>>(gatout, gat_b, N, DOUT);
    {
        dim3 blk(64, 4);
        int grid = (E + N + 3) / 4;
        gat_passC<<<grid, blk>>>(ei, logits, denom, gath, gatout, E);
    }

    // ---- SAGE 1 ----
    cudaMemsetAsync(agg, 0, (size_t)N * DHID * sizeof(float));
    sage_scatter<<<elEdgeBlocks, T>>>(h1, ei, agg, E, DHID);
    scale_rows<<<(N * DHID + T - 1) / T, T>>>(agg, deg, N, DHID);
    launch_gemm(agg, s1wl, s1b, s1, N, DHID, DOUT, 0, 0);
    launch_gemm(h1, s1wr, nullptr, s1, N, DHID, DOUT, 1, 1);  // += , relu

    // ---- SAGE 2 ----
    cudaMemsetAsync(agg2, 0, (size_t)N * DOUT * sizeof(float));
    sage_scatter<<<elEdgeBlocks, T>>>(s1, ei, agg2, E, DOUT);
    scale_rows<<<(N * DOUT + T - 1) / T, T>>>(agg2, deg, N, DOUT);
    launch_gemm(agg2, s2wl, s2b, s2, N, DOUT, DOUT, 0, 0);
    launch_gemm(s1, s2wr, nullptr, s2, N, DOUT, DOUT, 1, 0);  // += , no relu

    // ---- projection: emb = [gat | s2] @ projw + projb ----
    launch_gemm(gatout, projw, projb, emb, N, DOUT, DOUT, 0, 0);
    launch_gemm(s2, projw + 64 * DOUT, nullptr, emb, N, DOUT, DOUT, 1, 0);

    // ---- global mean pool ----
    cudaMemsetAsync(out, 0, (size_t)G * DOUT * sizeof(float));
    cudaMemsetAsync(cnt, 0, GG * sizeof(float));
    pool_sum<<<(N * DOUT + T - 1) / T, T>>>(emb, batch, out, cnt, N);
    pool_div<<<(G * DOUT + T - 1) / T, T>>>(out, cnt, G);
}

// round 2
// speedup vs baseline: 2.0195x; 2.0195x over previous
#include <cuda_runtime.h>
#include <math.h>
#include <stdint.h>

#define NN 20000
#define EE 320000
#define DIN 128
#define DHID 128
#define DOUT 64
#define HEADS 8
#define GG 64

// ---------------- scratch ----------------
__device__ int   g_deg[NN];
__device__ int   g_rowstart[NN + 1];
__device__ int   g_cursor[NN];
__device__ int   g_csr_src[EE];
__device__ float g_dinv[NN];            // rsqrt(deg+1)  (GCN, with self loop)
__device__ float g_sinv[NN];            // 1/max(deg,1)  (SAGE)
__device__ float g_tmp[NN * DHID];
__device__ float g_h0[NN * DHID];
__device__ float g_h1[NN * DHID];
__device__ float g_gath[NN * HEADS * DOUT];
__device__ float g_als[NN * HEADS];
__device__ float g_ald[NN * HEADS];
__device__ float g_ev[EE * HEADS];
__device__ float g_gatout[NN * DOUT];
__device__ float g_agg[NN * DHID];
__device__ float g_s1[NN * DOUT];
__device__ float g_agg2[NN * DOUT];
__device__ float g_s2[NN * DOUT];
__device__ float g_pooled[GG * 128];
__device__ float g_cnt[GG];

// ---------------- float4 helpers ----------------
__device__ __forceinline__ float4 f4mul(float4 a, float s) {
    return make_float4(a.x * s, a.y * s, a.z * s, a.w * s);
}
__device__ __forceinline__ void f4fma(float4& acc, float4 a, float s) {
    acc.x += a.x * s; acc.y += a.y * s; acc.z += a.z * s; acc.w += a.w * s;
}
__device__ __forceinline__ void f4add(float4& acc, float4 a) {
    acc.x += a.x; acc.y += a.y; acc.z += a.z; acc.w += a.w;
}

struct F8 { float v[8]; };
__device__ __forceinline__ F8 ld8(const float* p) {
    F8 r;
    float4 a = *(const float4*)p;
    float4 b = *(const float4*)(p + 4);
    r.v[0]=a.x; r.v[1]=a.y; r.v[2]=a.z; r.v[3]=a.w;
    r.v[4]=b.x; r.v[5]=b.y; r.v[6]=b.z; r.v[7]=b.w;
    return r;
}

// ---------------- GEMM: C[N,K] = A[N,M] @ W[M,K] (+b)(+=)(relu) ----------------
template<int M, int K, int R>
__global__ void __launch_bounds__((K / 4) * (R / 8))
gemm_t(const float* __restrict__ A, const float* __restrict__ W,
       const float* __restrict__ b, float* __restrict__ C,
       int N, int accum, int relu) {
    constexpr int K4 = K / 4, TYN = R / 8, NT = K4 * TYN;
    __shared__ float As[R * M];
    int tid = threadIdx.x;
    int tx = tid % K4, ty = tid / K4;
    int row0 = blockIdx.x * R;

    const float4* Ag = (const float4*)(A + (size_t)row0 * M);
    float4* Asv = (float4*)As;
    int valid_rows = N - row0; if (valid_rows > R) valid_rows = R;
    int limit4 = valid_rows > 0 ? valid_rows * (M / 4) : 0;
    constexpr int TOT4 = R * M / 4;
    for (int i = tid; i < TOT4; i += NT)
        Asv[i] = (i < limit4) ? Ag[i] : make_float4(0.f, 0.f, 0.f, 0.f);
    __syncthreads();

    float4 acc[8];
#pragma unroll
    for (int r = 0; r < 8; r++) acc[r] = make_float4(0.f, 0.f, 0.f, 0.f);

    const float4* Wv = (const float4*)W;
#pragma unroll 4
    for (int m = 0; m < M; m += 4) {
        float4 w0 = Wv[(size_t)(m + 0) * K4 + tx];
        float4 w1 = Wv[(size_t)(m + 1) * K4 + tx];
        float4 w2 = Wv[(size_t)(m + 2) * K4 + tx];
        float4 w3 = Wv[(size_t)(m + 3) * K4 + tx];
#pragma unroll
        for (int r = 0; r < 8; r++) {
            float4 a = *(const float4*)&As[(ty * 8 + r) * M + m];
            acc[r].x += a.x * w0.x + a.y * w1.x + a.z * w2.x + a.w * w3.x;
            acc[r].y += a.x * w0.y + a.y * w1.y + a.z * w2.y + a.w * w3.y;
            acc[r].z += a.x * w0.z + a.y * w1.z + a.z * w2.z + a.w * w3.z;
            acc[r].w += a.x * w0.w + a.y * w1.w + a.z * w2.w + a.w * w3.w;
        }
    }

    float4 bv = b ? ((const float4*)b)[tx] : make_float4(0.f, 0.f, 0.f, 0.f);
#pragma unroll
    for (int r = 0; r < 8; r++) {
        int row = row0 + ty * 8 + r;
        if (row >= N) continue;
        float4 v = acc[r];
        f4add(v, bv);
        float4* cp = (float4*)&C[(size_t)row * K + tx * 4];
        if (accum) { float4 c = *cp; f4add(v, c); }
        if (relu) {
            v.x = fmaxf(v.x, 0.f); v.y = fmaxf(v.y, 0.f);
            v.z = fmaxf(v.z, 0.f); v.w = fmaxf(v.w, 0.f);
        }
        *cp = v;
    }
}

// ---------------- CSR build ----------------
__global__ void deg_kernel(const int* __restrict__ ei, int* __restrict__ deg, int E) {
    int i = blockIdx.x * blockDim.x + threadIdx.x;
    if (i < E) atomicAdd(&deg[ei[E + i]], 1);
}

__global__ void scan_kernel(const int* __restrict__ deg, int* __restrict__ rowstart,
                            int* __restrict__ cursor, float* __restrict__ dinv,
                            float* __restrict__ sinv, int N) {
    __shared__ int sums[1024];
    int tid = threadIdx.x;
    int CH = (N + 1023) >> 10;
    int i0 = tid * CH;
    int iend = min(i0 + CH, N);
    int s = 0;
    for (int i = i0; i < iend; i++) s += deg[i];
    sums[tid] = s;
    __syncthreads();
    for (int off = 1; off < 1024; off <<= 1) {
        int v = (tid >= off) ? sums[tid - off] : 0;
        __syncthreads();
        sums[tid] += v;
        __syncthreads();
    }
    int run = tid ? sums[tid - 1] : 0;
    for (int i = i0; i < iend; i++) {
        int d = deg[i];
        rowstart[i] = run;
        cursor[i] = run;
        dinv[i] = rsqrtf((float)d + 1.0f);
        sinv[i] = 1.0f / fmaxf((float)d, 1.0f);
        run += d;
    }
    if (tid == 1023) rowstart[N] = sums[1023];
}

__global__ void csr_fill(const int* __restrict__ ei, int* __restrict__ cursor,
                         int* __restrict__ csr_src, int E) {
    int i = blockIdx.x * blockDim.x + threadIdx.x;
    if (i >= E) return;
    int s = ei[i], d = ei[E + i];
    int pos = atomicAdd(&cursor[d], 1);
    csr_src[pos] = s;
}

// ---------------- GCN gather (fused self-loop + bias + relu) ----------------
__global__ void gcn_gather(const float* __restrict__ tmp, const int* __restrict__ csr,
                           const int* __restrict__ rowstart, const float* __restrict__ dinv,
                           const float* __restrict__ b, float* __restrict__ h, int N) {
    int wid = (blockIdx.x * blockDim.x + threadIdx.x) >> 5;
    int lane = threadIdx.x & 31;
    if (wid >= N) return;
    int n = wid;
    float dn = dinv[n];
    float4 acc = f4mul(((const float4*)(tmp + (size_t)n * 128))[lane], dn * dn);
    int e = rowstart[n], e1 = rowstart[n + 1];
    for (; e + 1 < e1; e += 2) {
        int sA = csr[e], sB = csr[e + 1];
        float nA = dinv[sA] * dn, nB = dinv[sB] * dn;
        float4 vA = ((const float4*)(tmp + (size_t)sA * 128))[lane];
        float4 vB = ((const float4*)(tmp + (size_t)sB * 128))[lane];
        f4fma(acc, vA, nA);
        f4fma(acc, vB, nB);
    }
    if (e < e1) {
        int sA = csr[e];
        float4 vA = ((const float4*)(tmp + (size_t)sA * 128))[lane];
        f4fma(acc, vA, dinv[sA] * dn);
    }
    float4 bv = ((const float4*)b)[lane];
    f4add(acc, bv);
    acc.x = fmaxf(acc.x, 0.f); acc.y = fmaxf(acc.y, 0.f);
    acc.z = fmaxf(acc.z, 0.f); acc.w = fmaxf(acc.w, 0.f);
    ((float4*)(h + (size_t)n * 128))[lane] = acc;
}

// ---------------- SAGE gathers (mean agg, no self loop) ----------------
__global__ void sage_gather128(const float* __restrict__ x, const int* __restrict__ csr,
                               const int* __restrict__ rowstart, const float* __restrict__ sinv,
                               float* __restrict__ out, int N) {
    int wid = (blockIdx.x * blockDim.x + threadIdx.x) >> 5;
    int lane = threadIdx.x & 31;
    if (wid >= N) return;
    int n = wid;
    float4 acc = make_float4(0.f, 0.f, 0.f, 0.f);
    int e = rowstart[n], e1 = rowstart[n + 1];
    for (; e + 1 < e1; e += 2) {
        int sA = csr[e], sB = csr[e + 1];
        float4 vA = ((const float4*)(x + (size_t)sA * 128))[lane];
        float4 vB = ((const float4*)(x + (size_t)sB * 128))[lane];
        f4add(acc, vA); f4add(acc, vB);
    }
    if (e < e1) {
        float4 vA = ((const float4*)(x + (size_t)csr[e] * 128))[lane];
        f4add(acc, vA);
    }
    ((float4*)(out + (size_t)n * 128))[lane] = f4mul(acc, sinv[n]);
}

__global__ void sage_gather64(const float* __restrict__ x, const int* __restrict__ csr,
                              const int* __restrict__ rowstart, const float* __restrict__ sinv,
                              float* __restrict__ out, int N) {
    int wid = (blockIdx.x * blockDim.x + threadIdx.x) >> 5;
    int lane = threadIdx.x & 31;
    if (wid >= N) return;
    int n = wid;
    float2 acc = make_float2(0.f, 0.f);
    int e = rowstart[n], e1 = rowstart[n + 1];
    for (; e + 1 < e1; e += 2) {
        int sA = csr[e], sB = csr[e + 1];
        float2 vA = ((const float2*)(x + (size_t)sA * 64))[lane];
        float2 vB = ((const float2*)(x + (size_t)sB * 64))[lane];
        acc.x += vA.x + vB.x; acc.y += vA.y + vB.y;
    }
    if (e < e1) {
        float2 vA = ((const float2*)(x + (size_t)csr[e] * 64))[lane];
        acc.x += vA.x; acc.y += vA.y;
    }
    float s = sinv[n];
    ((float2*)(out + (size_t)n * 64))[lane] = make_float2(acc.x * s, acc.y * s);
}

// ---------------- GAT ----------------
__global__ void gat_al_kernel(const float* __restrict__ gath, const float* __restrict__ asrc,
                              const float* __restrict__ adst, float* __restrict__ als,
                              float* __restrict__ ald, int N) {
    int i = blockIdx.x * blockDim.x + threadIdx.x;
    if (i >= N * HEADS) return;
    int n = i >> 3, h = i & 7;
    const float4* hp = (const float4*)(gath + (size_t)n * 512 + h * 64);
    const float4* sp = (const float4*)(asrc + h * 64);
    const float4* dp = (const float4*)(adst + h * 64);
    float a = 0.f, b = 0.f;
#pragma unroll
    for (int k = 0; k < 16; k++) {
        float4 hv = hp[k], sv = sp[k], dv = dp[k];
        a += hv.x * sv.x + hv.y * sv.y + hv.z * sv.z + hv.w * sv.w;
        b += hv.x * dv.x + hv.y * dv.y + hv.z * dv.z + hv.w * dv.w;
    }
    als[i] = a;
    ald[i] = b;
}

// Fused per-node GAT: segment max, softmax denom, weighted head-mean aggregation.
__global__ void gat_fused(const int* __restrict__ csr, const int* __restrict__ rowstart,
                          const float* __restrict__ als, const float* __restrict__ ald,
                          const float* __restrict__ gath, const float* __restrict__ gat_b,
                          float* __restrict__ ev, float* __restrict__ gatout, int N) {
    int wid = (blockIdx.x * blockDim.x + threadIdx.x) >> 5;
    int lane = threadIdx.x & 31;
    if (wid >= N) return;
    int n = wid;
    int e0 = rowstart[n], e1 = rowstart[n + 1];

    F8 aldn = ld8(ald + (size_t)n * 8);
    F8 alsn = ld8(als + (size_t)n * 8);

    // self logit
    float ls[8], lmax[8];
#pragma unroll
    for (int h = 0; h < 8; h++) {
        float l = alsn.v[h] + aldn.v[h];
        ls[h] = (l > 0.f) ? l : 0.2f * l;
        lmax[h] = ls[h];
    }
    // pass 1: max over in-edges (lane-parallel)
    for (int e = e0 + lane; e < e1; e += 32) {
        F8 a = ld8(als + (size_t)csr[e] * 8);
#pragma unroll
        for (int h = 0; h < 8; h++) {
            float l = a.v[h] + aldn.v[h];
            l = (l > 0.f) ? l : 0.2f * l;
            lmax[h] = fmaxf(lmax[h], l);
        }
    }
#pragma unroll
    for (int off = 16; off; off >>= 1)
#pragma unroll
        for (int h = 0; h < 8; h++)
            lmax[h] = fmaxf(lmax[h], __shfl_xor_sync(0xffffffffu, lmax[h], off));

    // pass 2: exp + denom, stash exp values per edge
    float den[8];
#pragma unroll
    for (int h = 0; h < 8; h++)
        den[h] = (lane == 0) ? __expf(ls[h] - lmax[h]) : 0.f;
    for (int e = e0 + lane; e < e1; e += 32) {
        F8 a = ld8(als + (size_t)csr[e] * 8);
        float4 oA, oB;
        float t[8];
#pragma unroll
        for (int h = 0; h < 8; h++) {
            float l = a.v[h] + aldn.v[h];
            l = (l > 0.f) ? l : 0.2f * l;
            float x = __expf(l - lmax[h]);
            den[h] += x;
            t[h] = x;
        }
        oA = make_float4(t[0], t[1], t[2], t[3]);
        oB = make_float4(t[4], t[5], t[6], t[7]);
        *(float4*)(ev + (size_t)e * 8) = oA;
        *(float4*)(ev + (size_t)e * 8 + 4) = oB;
    }
#pragma unroll
    for (int off = 16; off; off >>= 1)
#pragma unroll
        for (int h = 0; h < 8; h++)
            den[h] += __shfl_xor_sync(0xffffffffu, den[h], off);

    float rden[8];
#pragma unroll
    for (int h = 0; h < 8; h++) rden[h] = 1.0f / den[h];

    __threadfence_block();
    __syncwarp();

    // pass 3: aggregate 64 channels (2 per lane), edges uniform across warp
    int c0 = lane * 2;
    float2 acc = make_float2(0.f, 0.f);
    // self edge
#pragma unroll
    for (int h = 0; h < 8; h++) {
        float a = __expf(ls[h] - lmax[h]) * rden[h];
        float2 g = *(const float2*)(gath + (size_t)n * 512 + h * 64 + c0);
        acc.x += a * g.x; acc.y += a * g.y;
    }
    for (int e = e0; e < e1; e++) {
        int s = csr[e];
        F8 x = ld8(ev + (size_t)e * 8);
        const float* gr = gath + (size_t)s * 512 + c0;
#pragma unroll
        for (int h = 0; h < 8; h++) {
            float a = x.v[h] * rden[h];
            float2 g = *(const float2*)(gr + h * 64);
            acc.x += a * g.x; acc.y += a * g.y;
        }
    }
    gatout[(size_t)n * 64 + c0]     = acc.x * 0.125f + gat_b[c0];
    gatout[(size_t)n * 64 + c0 + 1] = acc.y * 0.125f + gat_b[c0 + 1];
}

// ---------------- pooling (batch is sorted -> run-length pre-aggregation) ----------------
__global__ void pool_kernel(const float* __restrict__ gatout, const float* __restrict__ s2,
                            const int* __restrict__ batch, float* __restrict__ pooled,
                            float* __restrict__ cnt, int N) {
    int c = threadIdx.x;              // 0..127
    int n0 = blockIdx.x * 32;
    if (n0 >= N) return;
    int nend = min(n0 + 32, N);
    int cur = batch[n0];
    float acc = 0.f, cc = 0.f;
    for (int n = n0; n < nend; n++) {
        int g = batch[n];
        if (g != cur) {
            atomicAdd(&pooled[cur * 128 + c], acc);
            if (c == 0) atomicAdd(&cnt[cur], cc);
            acc = 0.f; cc = 0.f; cur = g;
        }
        acc += (c < 64) ? gatout[(size_t)n * 64 + c] : s2[(size_t)n * 64 + (c - 64)];
        cc += 1.f;
    }
    atomicAdd(&pooled[cur * 128 + c], acc);
    if (c == 0) atomicAdd(&cnt[cur], cc);
}

// out[g,c] = (pooled[g,:]/cnt[g]) @ projw + projb
__global__ void final_kernel(const float* __restrict__ pooled, const float* __restrict__ cnt,
                             const float* __restrict__ projw, const float* __restrict__ projb,
                             float* __restrict__ out) {
    int g = blockIdx.x, c = threadIdx.x;   // 64 x 64
    float inv = 1.0f / fmaxf(cnt[g], 1.0f);
    float acc = 0.f;
#pragma unroll 8
    for (int k = 0; k < 128; k++)
        acc += pooled[g * 128 + k] * projw[k * 64 + c];
    out[g * 64 + c] = acc * inv + projb[c];
}

// ---------------- launch ----------------
extern "C" void kernel_launch(void* const* d_in, const int* in_sizes, int n_in,
                              void* d_out, int out_size) {
    const float* x       = (const float*)d_in[0];
    const int*   ei      = (const int*)d_in[1];
    const int*   batch   = (const int*)d_in[2];
    const float* gcn_w0  = (const float*)d_in[3];
    const float* gcn_b0  = (const float*)d_in[4];
    const float* gcn_w1  = (const float*)d_in[5];
    const float* gcn_b1  = (const float*)d_in[6];
    const float* gat_w   = (const float*)d_in[7];
    const float* att_src = (const float*)d_in[8];
    const float* att_dst = (const float*)d_in[9];
    const float* gat_b   = (const float*)d_in[10];
    const float* s1wl    = (const float*)d_in[11];
    const float* s1wr    = (const float*)d_in[12];
    const float* s1b     = (const float*)d_in[13];
    const float* s2wl    = (const float*)d_in[14];
    const float* s2wr    = (const float*)d_in[15];
    const float* s2b     = (const float*)d_in[16];
    const float* projw   = (const float*)d_in[17];
    const float* projb   = (const float*)d_in[18];

    const int N = in_sizes[0] / DIN;
    const int E = in_sizes[1] / 2;
    float* out = (float*)d_out;

    int *deg, *rowstart, *cursor, *csr;
    float *dinv, *sinv, *tmp, *h0, *h1, *gath, *als, *ald, *ev, *gatout,
          *agg, *s1, *agg2, *s2, *pooled, *cnt;
    cudaGetSymbolAddress((void**)&deg, g_deg);
    cudaGetSymbolAddress((void**)&rowstart, g_rowstart);
    cudaGetSymbolAddress((void**)&cursor, g_cursor);
    cudaGetSymbolAddress((void**)&csr, g_csr_src);
    cudaGetSymbolAddress((void**)&dinv, g_dinv);
    cudaGetSymbolAddress((void**)&sinv, g_sinv);
    cudaGetSymbolAddress((void**)&tmp, g_tmp);
    cudaGetSymbolAddress((void**)&h0, g_h0);
    cudaGetSymbolAddress((void**)&h1, g_h1);
    cudaGetSymbolAddress((void**)&gath, g_gath);
    cudaGetSymbolAddress((void**)&als, g_als);
    cudaGetSymbolAddress((void**)&ald, g_ald);
    cudaGetSymbolAddress((void**)&ev, g_ev);
    cudaGetSymbolAddress((void**)&gatout, g_gatout);
    cudaGetSymbolAddress((void**)&agg, g_agg);
    cudaGetSymbolAddress((void**)&s1, g_s1);
    cudaGetSymbolAddress((void**)&agg2, g_agg2);
    cudaGetSymbolAddress((void**)&s2, g_s2);
    cudaGetSymbolAddress((void**)&pooled, g_pooled);
    cudaGetSymbolAddress((void**)&cnt, g_cnt);

    const int T = 256;
    int nodeWarpBlocks = (N * 32 + T - 1) / T;

    // ---- CSR build ----
    cudaMemsetAsync(deg, 0, N * sizeof(int));
    deg_kernel<<<(E + T - 1) / T, T>>>(ei, deg, E);
    scan_kernel<<<1, 1024>>>(deg, rowstart, cursor, dinv, sinv, N);
    csr_fill<<<(E + T - 1) / T, T>>>(ei, cursor, csr, E);

    // ---- GCN layer 0 ----
    gemm_t<128, 128, 64><<<(N + 63) / 64, 256>>>(x, gcn_w0, nullptr, tmp, N, 0, 0);
    gcn_gather<<<nodeWarpBlocks, T>>>(tmp, csr, rowstart, dinv, gcn_b0, h0, N);

    // ---- GCN layer 1 ----
    gemm_t<128, 128, 64><<<(N + 63) / 64, 256>>>(h0, gcn_w1, nullptr, tmp, N, 0, 0);
    gcn_gather<<<nodeWarpBlocks, T>>>(tmp, csr, rowstart, dinv, gcn_b1, h1, N);

    // ---- GAT ----
    gemm_t<128, 512, 16><<<(N + 15) / 16, 256>>>(h1, gat_w, nullptr, gath, N, 0, 0);
    gat_al_kernel<<<(N * HEADS + T - 1) / T, T>>>(gath, att_src, att_dst, als, ald, N);
    gat_fused<<<nodeWarpBlocks, T>>>(csr, rowstart, als, ald, gath, gat_b, ev, gatout, N);

    // ---- SAGE 1 ----
    sage_gather128<<<nodeWarpBlocks, T>>>(h1, csr, rowstart, sinv, agg, N);
    gemm_t<128, 64, 64><<<(N + 63) / 64, 128>>>(agg, s1wl, s1b, s1, N, 0, 0);
    gemm_t<128, 64, 64><<<(N + 63) / 64, 128>>>(h1, s1wr, nullptr, s1, N, 1, 1);

    // ---- SAGE 2 ----
    sage_gather64<<<nodeWarpBlocks, T>>>(s1, csr, rowstart, sinv, agg2, N);
    gemm_t<64, 64, 64><<<(N + 63) / 64, 128>>>(agg2, s2wl, s2b, s2, N, 0, 0);
    gemm_t<64, 64, 64><<<(N + 63) / 64, 128>>>(s1, s2wr, nullptr, s2, N, 1, 0);

    // ---- pool then project (mean-pool commutes with linear proj) ----
    cudaMemsetAsync(pooled, 0, GG * 128 * sizeof(float));
    cudaMemsetAsync(cnt, 0, GG * sizeof(float));
    pool_kernel<<<(N + 31) / 32, 128>>>(gatout, s2, batch, pooled, cnt, N);
    final_kernel<<<GG, 64>>>(pooled, cnt, projw, projb, out);
}